// round 3
// baseline (speedup 1.0000x reference)
#include <cuda_runtime.h>
#include <math.h>

// Problem constants
#define VV 27
#define EE 64
#define HH 128
#define BB 256
#define SE 512
#define SD 512

typedef unsigned long long ull;

// Scratch for decoder hidden states: [B, S_DEC, H] fp32 = 64 MB.
__device__ float g_dec_h[(size_t)BB * SD * HH];

// ---- packed fp32x2 helpers (sm_103a FFMA2) ----
__device__ __forceinline__ void ffma2(ull& d, ull a, ull b) {
    asm("fma.rn.f32x2 %0, %1, %2, %0;" : "+l"(d) : "l"(a), "l"(b));
}
__device__ __forceinline__ ull pack2(float x, float y) {
    ull r; asm("mov.b64 %0, {%1, %2};" : "=l"(r) : "f"(x), "f"(y)); return r;
}
__device__ __forceinline__ float2 unpack2(ull v) {
    float2 r; asm("mov.b64 {%0, %1}, %2;" : "=f"(r.x), "=f"(r.y) : "l"(v)); return r;
}

// Fast-but-accurate tanh: 1 - 2/(exp(2x)+1). abs err ~1e-6.
__device__ __forceinline__ float fast_tanh(float x) {
    float e = __expf(x * 2.0f);
    return 1.0f - __fdividef(2.0f, e + 1.0f);
}

// =====================================================================
// Kernel 1: fused encoder+decoder scan.
// 128 CTAs x 512 threads. Thread = (row grp, unit j, K-half s):
//   tid>>8 = row within CTA, (tid&255)>>1 = j, tid&1 = s.
// Each thread: half-dot (64 MACs = 32 FFMA2, Wh half-column in 32 u64
// regs), then shfl_xor(1) combines halves. 4 warps/SMSP hide latency.
// =====================================================================
__global__ void __launch_bounds__(512, 1) scan_kernel(
    const int*   __restrict__ enc_ids, const int* __restrict__ dec_ids,
    const float* __restrict__ embed,
    const float* __restrict__ enc_Wx, const float* __restrict__ enc_Wh,
    const float* __restrict__ enc_b,
    const float* __restrict__ dec_Wx, const float* __restrict__ dec_Wh,
    const float* __restrict__ dec_b)
{
    __shared__ float tabE[VV][HH];                    // 13.5 KB
    __shared__ float tabD[VV][HH];                    // 13.5 KB
    __shared__ float emb_s[VV * EE];                  // 6.75 KB
    __shared__ __align__(16) float hbuf[2][2][HH];    // double-buffered h
    __shared__ int   idsE[2][SE];                     // 4 KB
    __shared__ int   idsD[2][SD];                     // 4 KB

    const int tid  = threadIdx.x;
    const int grp  = tid >> 8;            // row within CTA
    const int r    = tid & 255;
    const int j    = r >> 1;              // hidden unit
    const int s    = r & 1;               // K-half
    const int k0   = s * (HH / 2);        // this thread's K range start
    const int row0 = blockIdx.x * 2;
    const int row  = row0 + grp;

    // ---- stage embeddings + token ids ----
    for (int i = tid; i < VV * EE; i += 512) emb_s[i] = embed[i];
    for (int i = tid; i < SE; i += 512) {
        idsE[0][i] = enc_ids[(size_t)row0 * SE + i];
        idsE[1][i] = enc_ids[(size_t)(row0 + 1) * SE + i];
    }
    for (int i = tid; i < SD; i += 512) {
        idsD[0][i] = dec_ids[(size_t)row0 * SD + i];
        idsD[1][i] = dec_ids[(size_t)(row0 + 1) * SD + i];
    }
    __syncthreads();

    // ---- token tables: tab[v][h] = emb[v]@Wx[:,h] + b[h] ----
    for (int idx = tid; idx < VV * HH; idx += 512) {
        const int v = idx / HH;
        const int h = idx - v * HH;
        float sE = enc_b[h];
        float sD = dec_b[h];
        #pragma unroll 8
        for (int e = 0; e < EE; e++) {
            const float em = emb_s[v * EE + e];
            sE = fmaf(em, enc_Wx[e * HH + h], sE);
            sD = fmaf(em, dec_Wx[e * HH + h], sD);
        }
        tabE[v][h] = sE;
        tabD[v][h] = sD;
    }

    if (s == 0) hbuf[0][grp][j] = 0.0f;
    __syncthreads();

    // ---- encoder phase: packed half-column of Wh in 32 u64 regs ----
    ull w2[HH / 4];
    #pragma unroll
    for (int m = 0; m < HH / 4; m++)
        w2[m] = pack2(enc_Wh[(k0 + 2 * m) * HH + j],
                      enc_Wh[(k0 + 2 * m + 1) * HH + j]);

    int cur = 0;
    float tb = tabE[idsE[grp][0]][j];     // prefetched table entry
    for (int t = 0; t < SE; t++) {
        const ulonglong2* hq = (const ulonglong2*)(hbuf[cur][grp] + k0);
        ull a0 = 0, a1 = 0, a2 = 0, a3 = 0;
        #pragma unroll
        for (int q = 0; q < HH / 8; q += 2) {     // 8 iters of 2x ulonglong2
            ulonglong2 h0 = hq[q];
            ulonglong2 h1 = hq[q + 1];
            ffma2(a0, h0.x, w2[2 * q + 0]);
            ffma2(a1, h0.y, w2[2 * q + 1]);
            ffma2(a2, h1.x, w2[2 * q + 2]);
            ffma2(a3, h1.y, w2[2 * q + 3]);
        }
        // prefetch next step's table entry (id is h-independent)
        const int tn = (t + 1 < SE) ? t + 1 : t;
        const float tb_next = tabE[idsE[grp][tn]][j];

        float2 s0 = unpack2(a0), s1 = unpack2(a1), s2 = unpack2(a2), s3 = unpack2(a3);
        float part = ((s0.x + s0.y) + (s1.x + s1.y)) + ((s2.x + s2.y) + (s3.x + s3.y));
        float dot = part + __shfl_xor_sync(0xffffffffu, part, 1);
        const float hn = fast_tanh(dot + tb);
        if (s == 0) hbuf[cur ^ 1][grp][j] = hn;
        asm volatile("bar.sync %0, 256;" :: "r"(grp + 1) : "memory");
        cur ^= 1;
        tb = tb_next;
    }

    // ---- decoder phase ----
    #pragma unroll
    for (int m = 0; m < HH / 4; m++)
        w2[m] = pack2(dec_Wh[(k0 + 2 * m) * HH + j],
                      dec_Wh[(k0 + 2 * m + 1) * HH + j]);

    float* outrow = g_dec_h + (size_t)row * SD * HH;
    tb = tabD[idsD[grp][0]][j];
    for (int t = 0; t < SD; t++) {
        const ulonglong2* hq = (const ulonglong2*)(hbuf[cur][grp] + k0);
        ull a0 = 0, a1 = 0, a2 = 0, a3 = 0;
        #pragma unroll
        for (int q = 0; q < HH / 8; q += 2) {
            ulonglong2 h0 = hq[q];
            ulonglong2 h1 = hq[q + 1];
            ffma2(a0, h0.x, w2[2 * q + 0]);
            ffma2(a1, h0.y, w2[2 * q + 1]);
            ffma2(a2, h1.x, w2[2 * q + 2]);
            ffma2(a3, h1.y, w2[2 * q + 3]);
        }
        const int tn = (t + 1 < SD) ? t + 1 : t;
        const float tb_next = tabD[idsD[grp][tn]][j];

        float2 s0 = unpack2(a0), s1 = unpack2(a1), s2 = unpack2(a2), s3 = unpack2(a3);
        float part = ((s0.x + s0.y) + (s1.x + s1.y)) + ((s2.x + s2.y) + (s3.x + s3.y));
        float dot = part + __shfl_xor_sync(0xffffffffu, part, 1);
        const float hn = fast_tanh(dot + tb);
        if (s == 0) hbuf[cur ^ 1][grp][j] = hn;   // smem writer
        else        outrow[t * HH + j] = hn;      // global writer (parallel)
        asm volatile("bar.sync %0, 256;" :: "r"(grp + 1) : "memory");
        cur ^= 1;
        tb = tb_next;
    }
}

// =====================================================================
// Kernel 2: logits = dec_h @ dense_W + dense_b.
// [131072,128] x [128,27->32pad]. v=tid&31, 8 tokens/thread.
// launch_bounds(256,4): cap regs at 64 so smem (49KB) binds at 4 CTA/SM.
// =====================================================================
__global__ void __launch_bounds__(256, 4) logits_kernel(
    const float* __restrict__ dense_W, const float* __restrict__ dense_b,
    float* __restrict__ out)
{
    __shared__ __align__(16) float hs[64 * HH];   // 32 KB
    __shared__ ull w2s[(HH / 2) * 32];            // 16 KB: [pair p][v]

    const int tid = threadIdx.x;
    const int v   = tid & 31;
    const int tg  = tid >> 5;
    const size_t tok0 = (size_t)blockIdx.x * 64;

    // stage h tile (float4 coalesced)
    const float4* hsrc = (const float4*)(g_dec_h + tok0 * HH);
    float4* hdst = (float4*)hs;
    #pragma unroll
    for (int i = 0; i < 8; i++) hdst[tid + 256 * i] = hsrc[tid + 256 * i];

    // stage packed W: w2s[p*32+v] = (W[2p][v], W[2p+1][v]); pad v>=27 with 0
    for (int p = tg; p < HH / 2; p += 8) {
        float wa = (v < VV) ? dense_W[(2 * p) * VV + v] : 0.0f;
        float wb = (v < VV) ? dense_W[(2 * p + 1) * VV + v] : 0.0f;
        w2s[p * 32 + v] = pack2(wa, wb);
    }
    __syncthreads();

    ull acc[8];
    #pragma unroll
    for (int r = 0; r < 8; r++) acc[r] = 0;

    #pragma unroll
    for (int q = 0; q < HH / 4; q++) {
        const ull wA = w2s[(2 * q + 0) * 32 + v];
        const ull wB = w2s[(2 * q + 1) * 32 + v];
        #pragma unroll
        for (int r = 0; r < 8; r++) {
            const ulonglong2 hv =
                ((const ulonglong2*)(hs + (tg * 8 + r) * HH))[q];  // broadcast
            ffma2(acc[r], hv.x, wA);
            ffma2(acc[r], hv.y, wB);
        }
    }

    if (v < VV) {
        const float bias = dense_b[v];
        #pragma unroll
        for (int r = 0; r < 8; r++) {
            float2 sx = unpack2(acc[r]);
            out[(tok0 + (size_t)(tg * 8 + r)) * VV + v] = sx.x + sx.y + bias;
        }
    }
}

// =====================================================================
extern "C" void kernel_launch(void* const* d_in, const int* in_sizes, int n_in,
                              void* d_out, int out_size) {
    const int*   enc_ids = (const int*)  d_in[0];
    const int*   dec_ids = (const int*)  d_in[1];
    const float* embed   = (const float*)d_in[2];
    const float* enc_Wx  = (const float*)d_in[3];
    const float* enc_Wh  = (const float*)d_in[4];
    const float* enc_b   = (const float*)d_in[5];
    const float* dec_Wx  = (const float*)d_in[6];
    const float* dec_Wh  = (const float*)d_in[7];
    const float* dec_b   = (const float*)d_in[8];
    const float* dense_W = (const float*)d_in[9];
    const float* dense_b = (const float*)d_in[10];
    float* out = (float*)d_out;

    scan_kernel<<<BB / 2, 512>>>(enc_ids, dec_ids, embed,
                                 enc_Wx, enc_Wh, enc_b,
                                 dec_Wx, dec_Wh, dec_b);
    logits_kernel<<<(BB * SD) / 64, 256>>>(dense_W, dense_b, out);
}

// round 5
// speedup vs baseline: 1.5699x; 1.5699x over previous
#include <cuda_runtime.h>
#include <math.h>

// Problem constants
#define VV 27
#define EE 64
#define HH 128
#define BB 256
#define SE 512
#define SD 512

typedef unsigned long long ull;

// Scratch for decoder hidden states: [B, S_DEC, H] fp32 = 64 MB.
__device__ float g_dec_h[(size_t)BB * SD * HH];

// ---- packed fp32x2 helpers (sm_103a FFMA2) ----
__device__ __forceinline__ void ffma2(ull& d, ull a, ull b) {
    asm("fma.rn.f32x2 %0, %1, %2, %0;" : "+l"(d) : "l"(a), "l"(b));
}
__device__ __forceinline__ ull pack2(float x, float y) {
    ull r; asm("mov.b64 %0, {%1, %2};" : "=l"(r) : "f"(x), "f"(y)); return r;
}
__device__ __forceinline__ float2 unpack2(ull v) {
    float2 r; asm("mov.b64 {%0, %1}, %2;" : "=f"(r.x), "=f"(r.y) : "l"(v)); return r;
}

// Fast-but-accurate tanh: 1 - 2/(exp(2x)+1). abs err ~1e-6.
__device__ __forceinline__ float fast_tanh(float x) {
    float e = __expf(x * 2.0f);
    return 1.0f - __fdividef(2.0f, e + 1.0f);
}

// =====================================================================
// Kernel 1: fused encoder+decoder scan.
// 128 CTAs x 128 threads. Thread j computes hidden unit j for BOTH of
// the CTA's 2 batch rows. Wh column j (shared by both rows) lives in
// 64 packed u64 regs. One __syncthreads per step covers 2 rows; the two
// rows' reduce/tanh chains are independent -> ILP hides the tail.
// =====================================================================
__global__ void __launch_bounds__(128, 1) scan_kernel(
    const int*   __restrict__ enc_ids, const int* __restrict__ dec_ids,
    const float* __restrict__ embed,
    const float* __restrict__ enc_Wx, const float* __restrict__ enc_Wh,
    const float* __restrict__ enc_b,
    const float* __restrict__ dec_Wx, const float* __restrict__ dec_Wh,
    const float* __restrict__ dec_b)
{
    __shared__ float tabE[VV][HH];                    // 13.5 KB
    __shared__ float tabD[VV][HH];                    // 13.5 KB
    __shared__ float emb_s[VV * EE];                  // 6.75 KB
    __shared__ __align__(16) float hbuf[2][2][HH];    // [buf][row][j]
    __shared__ int   idsE[2][SE];                     // 4 KB
    __shared__ int   idsD[2][SD];                     // 4 KB

    const int j    = threadIdx.x;          // hidden unit
    const int row0 = blockIdx.x * 2;

    // ---- stage embeddings + token ids ----
    for (int i = j; i < VV * EE; i += 128) emb_s[i] = embed[i];
    for (int i = j; i < SE; i += 128) {
        idsE[0][i] = enc_ids[(size_t)row0 * SE + i];
        idsE[1][i] = enc_ids[(size_t)(row0 + 1) * SE + i];
    }
    for (int i = j; i < SD; i += 128) {
        idsD[0][i] = dec_ids[(size_t)row0 * SD + i];
        idsD[1][i] = dec_ids[(size_t)(row0 + 1) * SD + i];
    }
    __syncthreads();

    // ---- token tables: tab[v][h] = emb[v]@Wx[:,h] + b[h] ----
    for (int idx = j; idx < VV * HH; idx += 128) {
        const int v = idx / HH;
        const int h = idx - v * HH;
        float sE = enc_b[h];
        float sD = dec_b[h];
        #pragma unroll 8
        for (int e = 0; e < EE; e++) {
            const float em = emb_s[v * EE + e];
            sE = fmaf(em, enc_Wx[e * HH + h], sE);
            sD = fmaf(em, dec_Wx[e * HH + h], sD);
        }
        tabE[v][h] = sE;
        tabD[v][h] = sD;
    }

    hbuf[0][0][j] = 0.0f;
    hbuf[0][1][j] = 0.0f;
    __syncthreads();

    // ---- encoder phase: packed Wh column in 64 u64 regs (shared rows) ----
    ull w2[HH / 2];
    #pragma unroll
    for (int k = 0; k < HH / 2; k++)
        w2[k] = pack2(enc_Wh[(2 * k) * HH + j], enc_Wh[(2 * k + 1) * HH + j]);

    int cur = 0;
    float tb0 = tabE[idsE[0][0]][j];
    float tb1 = tabE[idsE[1][0]][j];
    for (int t = 0; t < SE; t++) {
        const ulonglong2* h0q = (const ulonglong2*)hbuf[cur][0];
        const ulonglong2* h1q = (const ulonglong2*)hbuf[cur][1];
        // fold table entry into accumulator init (one fewer chained add)
        ull a00 = pack2(tb0, 0.0f), a01 = 0;
        ull a10 = pack2(tb1, 0.0f), a11 = 0;
        #pragma unroll
        for (int q = 0; q < HH / 4; q++) {   // 32 ulonglong2 = full K=128
            ulonglong2 h0 = h0q[q];
            ulonglong2 h1 = h1q[q];
            ffma2(a00, h0.x, w2[2 * q + 0]);
            ffma2(a01, h0.y, w2[2 * q + 1]);
            ffma2(a10, h1.x, w2[2 * q + 0]);
            ffma2(a11, h1.y, w2[2 * q + 1]);
        }
        // prefetch next step's table entries (id is h-independent)
        const int tn = (t + 1 < SE) ? t + 1 : t;
        const float nb0 = tabE[idsE[0][tn]][j];
        const float nb1 = tabE[idsE[1][tn]][j];

        float2 s00 = unpack2(a00), s01 = unpack2(a01);
        float2 s10 = unpack2(a10), s11 = unpack2(a11);
        const float hn0 = fast_tanh((s00.x + s00.y) + (s01.x + s01.y));
        const float hn1 = fast_tanh((s10.x + s10.y) + (s11.x + s11.y));
        hbuf[cur ^ 1][0][j] = hn0;
        hbuf[cur ^ 1][1][j] = hn1;
        __syncthreads();
        cur ^= 1;
        tb0 = nb0; tb1 = nb1;
    }

    // ---- decoder phase ----
    #pragma unroll
    for (int k = 0; k < HH / 2; k++)
        w2[k] = pack2(dec_Wh[(2 * k) * HH + j], dec_Wh[(2 * k + 1) * HH + j]);

    float* outrow0 = g_dec_h + (size_t)row0 * SD * HH;
    float* outrow1 = g_dec_h + (size_t)(row0 + 1) * SD * HH;
    tb0 = tabD[idsD[0][0]][j];
    tb1 = tabD[idsD[1][0]][j];
    for (int t = 0; t < SD; t++) {
        const ulonglong2* h0q = (const ulonglong2*)hbuf[cur][0];
        const ulonglong2* h1q = (const ulonglong2*)hbuf[cur][1];
        ull a00 = pack2(tb0, 0.0f), a01 = 0;
        ull a10 = pack2(tb1, 0.0f), a11 = 0;
        #pragma unroll
        for (int q = 0; q < HH / 4; q++) {   // full K=128
            ulonglong2 h0 = h0q[q];
            ulonglong2 h1 = h1q[q];
            ffma2(a00, h0.x, w2[2 * q + 0]);
            ffma2(a01, h0.y, w2[2 * q + 1]);
            ffma2(a10, h1.x, w2[2 * q + 0]);
            ffma2(a11, h1.y, w2[2 * q + 1]);
        }
        const int tn = (t + 1 < SD) ? t + 1 : t;
        const float nb0 = tabD[idsD[0][tn]][j];
        const float nb1 = tabD[idsD[1][tn]][j];

        float2 s00 = unpack2(a00), s01 = unpack2(a01);
        float2 s10 = unpack2(a10), s11 = unpack2(a11);
        const float hn0 = fast_tanh((s00.x + s00.y) + (s01.x + s01.y));
        const float hn1 = fast_tanh((s10.x + s10.y) + (s11.x + s11.y));
        hbuf[cur ^ 1][0][j] = hn0;
        hbuf[cur ^ 1][1][j] = hn1;
        outrow0[t * HH + j] = hn0;           // coalesced, off-chain
        outrow1[t * HH + j] = hn1;
        __syncthreads();
        cur ^= 1;
        tb0 = nb0; tb1 = nb1;
    }
}

// =====================================================================
// Kernel 2: logits = dec_h @ dense_W + dense_b.  DRAM-bound -> maximize
// tiles in flight: 32-token tiles (16KB h + 16KB W = 32KB smem), 4096
// CTAs, low regs -> occupancy at the warp cap, high load MLP.
// v = tid&31 (27 live + 5 pad), tg = tid>>5 -> 4 tokens/thread.
// =====================================================================
__global__ void __launch_bounds__(256) logits_kernel(
    const float* __restrict__ dense_W, const float* __restrict__ dense_b,
    float* __restrict__ out)
{
    __shared__ __align__(16) float hs[32 * HH];   // 16 KB
    __shared__ ull w2s[(HH / 2) * 32];            // 16 KB: [pair p][v]

    const int tid = threadIdx.x;
    const int v   = tid & 31;
    const int tg  = tid >> 5;                     // 0..7, 4 tokens each
    const size_t tok0 = (size_t)blockIdx.x * 32;

    // stage h tile: 1024 float4 over 256 threads
    const float4* hsrc = (const float4*)(g_dec_h + tok0 * HH);
    float4* hdst = (float4*)hs;
    #pragma unroll
    for (int i = 0; i < 4; i++) hdst[tid + 256 * i] = hsrc[tid + 256 * i];

    // stage packed W: w2s[p*32+v] = (W[2p][v], W[2p+1][v]); pad v>=27 with 0
    for (int p = tg; p < HH / 2; p += 8) {
        float wa = (v < VV) ? dense_W[(2 * p) * VV + v] : 0.0f;
        float wb = (v < VV) ? dense_W[(2 * p + 1) * VV + v] : 0.0f;
        w2s[p * 32 + v] = pack2(wa, wb);
    }
    __syncthreads();

    ull acc[4];
    #pragma unroll
    for (int r = 0; r < 4; r++) acc[r] = 0;

    #pragma unroll
    for (int q = 0; q < HH / 4; q++) {
        const ull wA = w2s[(2 * q + 0) * 32 + v];
        const ull wB = w2s[(2 * q + 1) * 32 + v];
        #pragma unroll
        for (int r = 0; r < 4; r++) {
            const ulonglong2 hv =
                ((const ulonglong2*)(hs + (tg * 4 + r) * HH))[q];  // broadcast
            ffma2(acc[r], hv.x, wA);
            ffma2(acc[r], hv.y, wB);
        }
    }

    if (v < VV) {
        const float bias = dense_b[v];
        #pragma unroll
        for (int r = 0; r < 4; r++) {
            float2 sx = unpack2(acc[r]);
            out[(tok0 + (size_t)(tg * 4 + r)) * VV + v] = sx.x + sx.y + bias;
        }
    }
}

// =====================================================================
extern "C" void kernel_launch(void* const* d_in, const int* in_sizes, int n_in,
                              void* d_out, int out_size) {
    const int*   enc_ids = (const int*)  d_in[0];
    const int*   dec_ids = (const int*)  d_in[1];
    const float* embed   = (const float*)d_in[2];
    const float* enc_Wx  = (const float*)d_in[3];
    const float* enc_Wh  = (const float*)d_in[4];
    const float* enc_b   = (const float*)d_in[5];
    const float* dec_Wx  = (const float*)d_in[6];
    const float* dec_Wh  = (const float*)d_in[7];
    const float* dec_b   = (const float*)d_in[8];
    const float* dense_W = (const float*)d_in[9];
    const float* dense_b = (const float*)d_in[10];
    float* out = (float*)d_out;

    scan_kernel<<<BB / 2, 128>>>(enc_ids, dec_ids, embed,
                                 enc_Wx, enc_Wh, enc_b,
                                 dec_Wx, dec_Wh, dec_b);
    logits_kernel<<<(BB * SD) / 32, 256>>>(dense_W, dense_b, out);
}

// round 6
// speedup vs baseline: 1.6137x; 1.0279x over previous
#include <cuda_runtime.h>
#include <cuda_fp16.h>
#include <math.h>

// Problem constants
#define VV 27
#define EE 64
#define HH 128
#define BB 256
#define SE 512
#define SD 512

typedef unsigned long long ull;

// Scratch for decoder hidden states, fp16: [B, S_DEC, H] = 32 MB.
__device__ __half g_dec_h[(size_t)BB * SD * HH];

// ---- packed fp32x2 helpers (sm_103a FFMA2 / FADD2) ----
__device__ __forceinline__ void ffma2(ull& d, ull a, ull b) {
    asm("fma.rn.f32x2 %0, %1, %2, %0;" : "+l"(d) : "l"(a), "l"(b));
}
__device__ __forceinline__ ull addp2(ull a, ull b) {
    ull r; asm("add.rn.f32x2 %0, %1, %2;" : "=l"(r) : "l"(a), "l"(b)); return r;
}
__device__ __forceinline__ ull pack2(float x, float y) {
    ull r; asm("mov.b64 %0, {%1, %2};" : "=l"(r) : "f"(x), "f"(y)); return r;
}
__device__ __forceinline__ float2 unpack2(ull v) {
    float2 r; asm("mov.b64 {%0, %1}, %2;" : "=f"(r.x), "=f"(r.y) : "l"(v)); return r;
}

// Fast-but-accurate tanh: 1 - 2/(exp(2x)+1). abs err ~1e-6.
__device__ __forceinline__ float fast_tanh(float x) {
    float e = __expf(x * 2.0f);
    return 1.0f - __fdividef(2.0f, e + 1.0f);
}

// No-op kernel: shifts ncu's "-s 5 -c 1" capture window onto scan_kernel.
__global__ void nop_kernel() {}

// =====================================================================
// Kernel 1: fused encoder+decoder scan.
// 128 CTAs x 256 threads. grp = tid>>7 selects the CTA's batch row;
// thread computes hidden unit j = tid&127 of its row. Wh column in 64
// packed u64 regs (64 FFMA2/step). Per-row named barriers + a forced
// half-step stagger between the two row groups so one row's FMA-issue
// phase overlaps the other row's reduce/tanh/barrier tail.
// =====================================================================
__global__ void __launch_bounds__(256, 1) scan_kernel(
    const int*   __restrict__ enc_ids, const int* __restrict__ dec_ids,
    const float* __restrict__ embed,
    const float* __restrict__ enc_Wx, const float* __restrict__ enc_Wh,
    const float* __restrict__ enc_b,
    const float* __restrict__ dec_Wx, const float* __restrict__ dec_Wh,
    const float* __restrict__ dec_b)
{
    __shared__ float tabE[VV][HH];                    // 13.5 KB
    __shared__ float tabD[VV][HH];                    // 13.5 KB
    __shared__ float emb_s[VV * EE];                  // 6.75 KB
    __shared__ __align__(16) float hbuf[2][2][HH];    // [buf][row][j]
    __shared__ int   idsE[2][SE];                     // 4 KB
    __shared__ int   idsD[2][SD];                     // 4 KB

    const int tid  = threadIdx.x;
    const int grp  = tid >> 7;             // row within CTA
    const int j    = tid & (HH - 1);       // hidden unit
    const int row0 = blockIdx.x * 2;
    const int row  = row0 + grp;

    // ---- stage embeddings + token ids ----
    for (int i = tid; i < VV * EE; i += 256) emb_s[i] = embed[i];
    for (int i = tid; i < SE; i += 256) {
        idsE[0][i] = enc_ids[(size_t)row0 * SE + i];
        idsE[1][i] = enc_ids[(size_t)(row0 + 1) * SE + i];
    }
    for (int i = tid; i < SD; i += 256) {
        idsD[0][i] = dec_ids[(size_t)row0 * SD + i];
        idsD[1][i] = dec_ids[(size_t)(row0 + 1) * SD + i];
    }
    __syncthreads();

    // ---- token tables: tab[v][h] = emb[v]@Wx[:,h] + b[h] ----
    for (int idx = tid; idx < VV * HH; idx += 256) {
        const int v = idx / HH;
        const int h = idx - v * HH;
        float sE = enc_b[h];
        float sD = dec_b[h];
        #pragma unroll 8
        for (int e = 0; e < EE; e++) {
            const float em = emb_s[v * EE + e];
            sE = fmaf(em, enc_Wx[e * HH + h], sE);
            sD = fmaf(em, dec_Wx[e * HH + h], sD);
        }
        tabE[v][h] = sE;
        tabD[v][h] = sD;
    }

    if (grp == 0) { hbuf[0][0][j] = 0.0f; hbuf[0][1][j] = 0.0f; }
    __syncthreads();

    // ---- Wh column, packed (64 u64 regs) ----
    ull w2[HH / 2];
    #pragma unroll
    for (int k = 0; k < HH / 2; k++)
        w2[k] = pack2(enc_Wh[(2 * k) * HH + j], enc_Wh[(2 * k + 1) * HH + j]);

    // ---- forced anti-phase stagger: grp 1 burns ~192 cyc (serial chain) ----
    if (grp == 1) {
        ull dj = pack2(1.0f, 1.0f);
        #pragma unroll
        for (int k = 0; k < 48; k++) ffma2(dj, w2[k], w2[k + 1]);
        asm volatile("" :: "l"(dj));   // sink; never stored
    }

    // ---- encoder phase ----
    int cur = 0;
    float tb = tabE[idsE[grp][0]][j];
    for (int t = 0; t < SE; t++) {
        const ulonglong2* hq = (const ulonglong2*)hbuf[cur][grp];
        ull a0 = pack2(tb, 0.0f), a1 = 0, a2 = 0, a3 = 0;
        #pragma unroll
        for (int q = 0; q < HH / 4; q += 2) {     // 32 ulonglong2 = K=128
            ulonglong2 h0 = hq[q];
            ulonglong2 h1 = hq[q + 1];
            ffma2(a0, h0.x, w2[2 * q + 0]);
            ffma2(a1, h0.y, w2[2 * q + 1]);
            ffma2(a2, h1.x, w2[2 * q + 2]);
            ffma2(a3, h1.y, w2[2 * q + 3]);
        }
        const int tn = (t + 1 < SE) ? t + 1 : t;
        const float nb = tabE[idsE[grp][tn]][j];  // off-chain prefetch

        float2 s = unpack2(addp2(addp2(a0, a2), addp2(a1, a3)));
        const float hn = fast_tanh(s.x + s.y);
        hbuf[cur ^ 1][grp][j] = hn;
        asm volatile("bar.sync %0, 128;" :: "r"(grp + 1) : "memory");
        cur ^= 1;
        tb = nb;
    }

    // ---- decoder phase ----
    #pragma unroll
    for (int k = 0; k < HH / 2; k++)
        w2[k] = pack2(dec_Wh[(2 * k) * HH + j], dec_Wh[(2 * k + 1) * HH + j]);

    __half* outrow = g_dec_h + (size_t)row * SD * HH;
    tb = tabD[idsD[grp][0]][j];
    __half hprev = __float2half_rn(0.0f);
    int havest = 0;
    for (int t = 0; t < SD; t++) {
        const ulonglong2* hq = (const ulonglong2*)hbuf[cur][grp];
        ull a0 = pack2(tb, 0.0f), a1 = 0, a2 = 0, a3 = 0;
        #pragma unroll
        for (int q = 0; q < HH / 4; q += 2) {
            ulonglong2 h0 = hq[q];
            ulonglong2 h1 = hq[q + 1];
            ffma2(a0, h0.x, w2[2 * q + 0]);
            ffma2(a1, h0.y, w2[2 * q + 1]);
            ffma2(a2, h1.x, w2[2 * q + 2]);
            ffma2(a3, h1.y, w2[2 * q + 3]);
        }
        const int tn = (t + 1 < SD) ? t + 1 : t;
        const float nb = tabD[idsD[grp][tn]][j];

        float2 s = unpack2(addp2(addp2(a0, a2), addp2(a1, a3)));
        const float hn = fast_tanh(s.x + s.y);
        hbuf[cur ^ 1][grp][j] = hn;
        asm volatile("bar.sync %0, 128;" :: "r"(grp + 1) : "memory");
        // global store AFTER the barrier: fire-and-forget, off the chain
        outrow[t * HH + j] = __float2half_rn(hn);
        cur ^= 1;
        tb = nb;
        (void)hprev; (void)havest;
    }
}

// =====================================================================
// Kernel 2: logits = dec_h(fp16) @ dense_W + dense_b.
// 32-token tiles, 4096 CTAs. h staged fp16->fp32 into smem; inner loop
// FFMA2 with packed W pairs from smem (broadcast). v=tid&31, 4 tok/thr.
// =====================================================================
__global__ void __launch_bounds__(256) logits_kernel(
    const float* __restrict__ dense_W, const float* __restrict__ dense_b,
    float* __restrict__ out)
{
    __shared__ __align__(16) float hs[32 * HH];   // 16 KB (fp32 staging)
    __shared__ ull w2s[(HH / 2) * 32];            // 16 KB: [pair p][v]

    const int tid = threadIdx.x;
    const int v   = tid & 31;
    const int tg  = tid >> 5;                     // 0..7, 4 tokens each
    const size_t tok0 = (size_t)blockIdx.x * 32;

    // stage h tile: 4096 halfs = 512 uint4 (8 halfs each), 2 per thread
    const uint4* hsrc = (const uint4*)(g_dec_h + tok0 * HH);
    #pragma unroll
    for (int i = 0; i < 2; i++) {
        uint4 pk = hsrc[tid + 256 * i];
        float2 f0 = __half22float2(*(const __half2*)&pk.x);
        float2 f1 = __half22float2(*(const __half2*)&pk.y);
        float2 f2 = __half22float2(*(const __half2*)&pk.z);
        float2 f3 = __half22float2(*(const __half2*)&pk.w);
        float4* dst = ((float4*)hs) + (tid + 256 * i) * 2;
        dst[0] = make_float4(f0.x, f0.y, f1.x, f1.y);
        dst[1] = make_float4(f2.x, f2.y, f3.x, f3.y);
    }

    // stage packed W: w2s[p*32+v] = (W[2p][v], W[2p+1][v]); pad v>=27 with 0
    for (int p = tg; p < HH / 2; p += 8) {
        float wa = (v < VV) ? dense_W[(2 * p) * VV + v] : 0.0f;
        float wb = (v < VV) ? dense_W[(2 * p + 1) * VV + v] : 0.0f;
        w2s[p * 32 + v] = pack2(wa, wb);
    }
    __syncthreads();

    ull acc[4];
    #pragma unroll
    for (int r = 0; r < 4; r++) acc[r] = 0;

    #pragma unroll
    for (int q = 0; q < HH / 4; q++) {
        const ull wA = w2s[(2 * q + 0) * 32 + v];
        const ull wB = w2s[(2 * q + 1) * 32 + v];
        #pragma unroll
        for (int r = 0; r < 4; r++) {
            const ulonglong2 hv =
                ((const ulonglong2*)(hs + (tg * 4 + r) * HH))[q];  // broadcast
            ffma2(acc[r], hv.x, wA);
            ffma2(acc[r], hv.y, wB);
        }
    }

    if (v < VV) {
        const float bias = dense_b[v];
        #pragma unroll
        for (int r = 0; r < 4; r++) {
            float2 sx = unpack2(acc[r]);
            out[(tok0 + (size_t)(tg * 4 + r)) * VV + v] = sx.x + sx.y + bias;
        }
    }
}

// =====================================================================
extern "C" void kernel_launch(void* const* d_in, const int* in_sizes, int n_in,
                              void* d_out, int out_size) {
    const int*   enc_ids = (const int*)  d_in[0];
    const int*   dec_ids = (const int*)  d_in[1];
    const float* embed   = (const float*)d_in[2];
    const float* enc_Wx  = (const float*)d_in[3];
    const float* enc_Wh  = (const float*)d_in[4];
    const float* enc_b   = (const float*)d_in[5];
    const float* dec_Wx  = (const float*)d_in[6];
    const float* dec_Wh  = (const float*)d_in[7];
    const float* dec_b   = (const float*)d_in[8];
    const float* dense_W = (const float*)d_in[9];
    const float* dense_b = (const float*)d_in[10];
    float* out = (float*)d_out;

    // nop launches shift ncu's skip-5 capture onto scan_kernel (launch #6).
    nop_kernel<<<1, 1>>>();
    scan_kernel<<<BB / 2, 256>>>(enc_ids, dec_ids, embed,
                                 enc_Wx, enc_Wh, enc_b,
                                 dec_Wx, dec_Wh, dec_b);
    nop_kernel<<<1, 1>>>();
    logits_kernel<<<(BB * SD) / 32, 256>>>(dense_W, dense_b, out);
}

// round 8
// speedup vs baseline: 1.7532x; 1.0865x over previous
#include <cuda_runtime.h>
#include <cuda_fp16.h>
#include <cstdint>
#include <math.h>

// Problem constants
#define VV 27
#define EE 64
#define HH 128
#define BB 256
#define SE 512
#define SD 512

typedef unsigned long long ull;
typedef unsigned int u32;

// Scratch for decoder hidden states, fp16: [B, S_DEC, H] = 32 MB.
__device__ __half g_dec_h[(size_t)BB * SD * HH];

// ---- packed fp32x2 helpers (sm_103a FFMA2 / FADD2) ----
__device__ __forceinline__ void ffma2(ull& d, ull a, ull b) {
    asm("fma.rn.f32x2 %0, %1, %2, %0;" : "+l"(d) : "l"(a), "l"(b));
}
__device__ __forceinline__ ull addp2(ull a, ull b) {
    ull r; asm("add.rn.f32x2 %0, %1, %2;" : "=l"(r) : "l"(a), "l"(b)); return r;
}
__device__ __forceinline__ ull pack2(float x, float y) {
    ull r; asm("mov.b64 %0, {%1, %2};" : "=l"(r) : "f"(x), "f"(y)); return r;
}
__device__ __forceinline__ float2 unpack2(ull v) {
    float2 r; asm("mov.b64 {%0, %1}, %2;" : "=f"(r.x), "=f"(r.y) : "l"(v)); return r;
}

// Fast-but-accurate tanh: 1 - 2/(exp(2x)+1). abs err ~1e-6.
__device__ __forceinline__ float fast_tanh(float x) {
    float e = __expf(x * 2.0f);
    return 1.0f - __fdividef(2.0f, e + 1.0f);
}

// =====================================================================
// Kernel 1: fused encoder+decoder scan (best-known config).
// 128 CTAs x 256 threads; grp = tid>>7 = row, j = tid&127 = unit.
// Wh column in 64 packed u64 regs; FFMA2 inner loop.
// =====================================================================
__global__ void __launch_bounds__(256, 1) scan_kernel(
    const int*   __restrict__ enc_ids, const int* __restrict__ dec_ids,
    const float* __restrict__ embed,
    const float* __restrict__ enc_Wx, const float* __restrict__ enc_Wh,
    const float* __restrict__ enc_b,
    const float* __restrict__ dec_Wx, const float* __restrict__ dec_Wh,
    const float* __restrict__ dec_b)
{
    __shared__ float tabE[VV][HH];
    __shared__ float tabD[VV][HH];
    __shared__ float emb_s[VV * EE];
    __shared__ __align__(16) float hbuf[2][2][HH];
    __shared__ int   idsE[2][SE];
    __shared__ int   idsD[2][SD];

    const int tid  = threadIdx.x;
    const int grp  = tid >> 7;
    const int j    = tid & (HH - 1);
    const int row0 = blockIdx.x * 2;
    const int row  = row0 + grp;

    for (int i = tid; i < VV * EE; i += 256) emb_s[i] = embed[i];
    for (int i = tid; i < SE; i += 256) {
        idsE[0][i] = enc_ids[(size_t)row0 * SE + i];
        idsE[1][i] = enc_ids[(size_t)(row0 + 1) * SE + i];
    }
    for (int i = tid; i < SD; i += 256) {
        idsD[0][i] = dec_ids[(size_t)row0 * SD + i];
        idsD[1][i] = dec_ids[(size_t)(row0 + 1) * SD + i];
    }
    __syncthreads();

    for (int idx = tid; idx < VV * HH; idx += 256) {
        const int v = idx / HH;
        const int h = idx - v * HH;
        float sE = enc_b[h];
        float sD = dec_b[h];
        #pragma unroll 8
        for (int e = 0; e < EE; e++) {
            const float em = emb_s[v * EE + e];
            sE = fmaf(em, enc_Wx[e * HH + h], sE);
            sD = fmaf(em, dec_Wx[e * HH + h], sD);
        }
        tabE[v][h] = sE;
        tabD[v][h] = sD;
    }

    if (grp == 0) { hbuf[0][0][j] = 0.0f; hbuf[0][1][j] = 0.0f; }
    __syncthreads();

    ull w2[HH / 2];
    #pragma unroll
    for (int k = 0; k < HH / 2; k++)
        w2[k] = pack2(enc_Wh[(2 * k) * HH + j], enc_Wh[(2 * k + 1) * HH + j]);

    // ---- encoder phase ----
    int cur = 0;
    float tb = tabE[idsE[grp][0]][j];
    for (int t = 0; t < SE; t++) {
        const ulonglong2* hq = (const ulonglong2*)hbuf[cur][grp];
        ull a0 = pack2(tb, 0.0f), a1 = 0, a2 = 0, a3 = 0;
        #pragma unroll
        for (int q = 0; q < HH / 4; q += 2) {
            ulonglong2 h0 = hq[q];
            ulonglong2 h1 = hq[q + 1];
            ffma2(a0, h0.x, w2[2 * q + 0]);
            ffma2(a1, h0.y, w2[2 * q + 1]);
            ffma2(a2, h1.x, w2[2 * q + 2]);
            ffma2(a3, h1.y, w2[2 * q + 3]);
        }
        const int tn = (t + 1 < SE) ? t + 1 : t;
        const float nb = tabE[idsE[grp][tn]][j];

        float2 s = unpack2(addp2(addp2(a0, a2), addp2(a1, a3)));
        const float hn = fast_tanh(s.x + s.y);
        hbuf[cur ^ 1][grp][j] = hn;
        asm volatile("bar.sync %0, 128;" :: "r"(grp + 1) : "memory");
        cur ^= 1;
        tb = nb;
    }

    // ---- decoder phase ----
    #pragma unroll
    for (int k = 0; k < HH / 2; k++)
        w2[k] = pack2(dec_Wh[(2 * k) * HH + j], dec_Wh[(2 * k + 1) * HH + j]);

    __half* outrow = g_dec_h + (size_t)row * SD * HH;
    tb = tabD[idsD[grp][0]][j];
    for (int t = 0; t < SD; t++) {
        const ulonglong2* hq = (const ulonglong2*)hbuf[cur][grp];
        ull a0 = pack2(tb, 0.0f), a1 = 0, a2 = 0, a3 = 0;
        #pragma unroll
        for (int q = 0; q < HH / 4; q += 2) {
            ulonglong2 h0 = hq[q];
            ulonglong2 h1 = hq[q + 1];
            ffma2(a0, h0.x, w2[2 * q + 0]);
            ffma2(a1, h0.y, w2[2 * q + 1]);
            ffma2(a2, h1.x, w2[2 * q + 2]);
            ffma2(a3, h1.y, w2[2 * q + 3]);
        }
        const int tn = (t + 1 < SD) ? t + 1 : t;
        const float nb = tabD[idsD[grp][tn]][j];

        float2 s = unpack2(addp2(addp2(a0, a2), addp2(a1, a3)));
        const float hn = fast_tanh(s.x + s.y);
        hbuf[cur ^ 1][grp][j] = hn;
        asm volatile("bar.sync %0, 128;" :: "r"(grp + 1) : "memory");
        outrow[t * HH + j] = __float2half_rn(hn);   // off-chain store
        cur ^= 1;
        tb = nb;
    }
}

// =====================================================================
// Kernel 2: logits via tensor cores.
// [131072,128](fp16) x [128,27->32](fp16) + bias, fp32 accumulate.
// 1024 CTAs x 256 thr (8 warps). Tile: 128 tokens x 32 cols x k128.
// Warp w: rows [16w,16w+16), 4 n8 tiles, 8 k16 steps of
// mma.sync.m16n8k16. Fragments loaded from padded smem (stride 136).
// =====================================================================
__global__ void __launch_bounds__(256) logits_kernel(
    const float* __restrict__ dense_W, const float* __restrict__ dense_b,
    float* __restrict__ out)
{
    __shared__ __align__(16) __half hs[128 * 136];   // 34 KB h tile
    __shared__ __align__(16) __half w_s[32 * 136];   // 8.5 KB W^T
    __shared__ float bias_s[32];

    const int tid  = threadIdx.x;
    const int lane = tid & 31;
    const int wid  = tid >> 5;
    const size_t tok0 = (size_t)blockIdx.x * 128;

    // stage h tile: 2048 uint4 (16 per token row)
    const uint4* src = (const uint4*)(g_dec_h + tok0 * HH);
    #pragma unroll
    for (int i = 0; i < 8; i++) {
        const int idx = tid + 256 * i;
        const int row = idx >> 4, part = idx & 15;
        *(uint4*)&hs[row * 136 + part * 8] = src[idx];
    }

    // stage W^T fp16: w_s[v][k] = W[k][v]; pad v>=27 with 0
    for (int idx = tid; idx < 32 * 128; idx += 256) {
        const int v = idx & 31, k = idx >> 5;
        const float val = (v < VV) ? dense_W[k * VV + v] : 0.0f;
        w_s[v * 136 + k] = __float2half_rn(val);
    }
    if (tid < 32) bias_s[tid] = (tid < VV) ? dense_b[tid] : 0.0f;
    __syncthreads();

    const int gi = lane >> 2;      // groupID
    const int ci = lane & 3;       // thread-in-group
    const int m0 = wid * 16;

    float c[4][4] = {};
    #pragma unroll
    for (int ks = 0; ks < 8; ks++) {
        const int k = ks * 16 + ci * 2;
        const u32 a0 = *(const u32*)&hs[(m0 + gi)     * 136 + k];
        const u32 a1 = *(const u32*)&hs[(m0 + gi + 8) * 136 + k];
        const u32 a2 = *(const u32*)&hs[(m0 + gi)     * 136 + k + 8];
        const u32 a3 = *(const u32*)&hs[(m0 + gi + 8) * 136 + k + 8];
        #pragma unroll
        for (int nt = 0; nt < 4; nt++) {
            const int cc = nt * 8 + gi;
            const u32 b0 = *(const u32*)&w_s[cc * 136 + k];
            const u32 b1 = *(const u32*)&w_s[cc * 136 + k + 8];
            asm volatile(
                "mma.sync.aligned.m16n8k16.row.col.f32.f16.f16.f32 "
                "{%0,%1,%2,%3}, {%4,%5,%6,%7}, {%8,%9}, {%0,%1,%2,%3};"
                : "+f"(c[nt][0]), "+f"(c[nt][1]), "+f"(c[nt][2]), "+f"(c[nt][3])
                : "r"(a0), "r"(a1), "r"(a2), "r"(a3), "r"(b0), "r"(b1));
        }
    }

    // epilogue: add bias, store cols < 27
    #pragma unroll
    for (int nt = 0; nt < 4; nt++) {
        const int col = nt * 8 + ci * 2;
        const size_t r0 = tok0 + m0 + gi;
        const size_t r1 = r0 + 8;
        if (col < VV) {
            out[r0 * VV + col] = c[nt][0] + bias_s[col];
            out[r1 * VV + col] = c[nt][2] + bias_s[col];
        }
        if (col + 1 < VV) {
            out[r0 * VV + col + 1] = c[nt][1] + bias_s[col + 1];
            out[r1 * VV + col + 1] = c[nt][3] + bias_s[col + 1];
        }
    }
}

// =====================================================================
extern "C" void kernel_launch(void* const* d_in, const int* in_sizes, int n_in,
                              void* d_out, int out_size) {
    const int*   enc_ids = (const int*)  d_in[0];
    const int*   dec_ids = (const int*)  d_in[1];
    const float* embed   = (const float*)d_in[2];
    const float* enc_Wx  = (const float*)d_in[3];
    const float* enc_Wh  = (const float*)d_in[4];
    const float* enc_b   = (const float*)d_in[5];
    const float* dec_Wx  = (const float*)d_in[6];
    const float* dec_Wh  = (const float*)d_in[7];
    const float* dec_b   = (const float*)d_in[8];
    const float* dense_W = (const float*)d_in[9];
    const float* dense_b = (const float*)d_in[10];
    float* out = (float*)d_out;

    scan_kernel<<<BB / 2, 256>>>(enc_ids, dec_ids, embed,
                                 enc_Wx, enc_Wh, enc_b,
                                 dec_Wx, dec_Wh, dec_b);
    logits_kernel<<<(BB * SD) / 128, 256>>>(dense_W, dense_b, out);
}

// round 9
// speedup vs baseline: 1.8208x; 1.0385x over previous
#include <cuda_runtime.h>
#include <cuda_fp16.h>
#include <cstdint>
#include <math.h>

// Problem constants
#define VV 27
#define EE 64
#define HH 128
#define BB 256
#define SE 512
#define SD 512

typedef unsigned long long ull;
typedef unsigned int u32;

// Scratch for decoder hidden states, fp16: [B, S_DEC, H] = 32 MB.
__device__ __half g_dec_h[(size_t)BB * SD * HH];

// ---- packed fp32x2 helpers (sm_103a FFMA2 / FADD2) ----
__device__ __forceinline__ void ffma2(ull& d, ull a, ull b) {
    asm("fma.rn.f32x2 %0, %1, %2, %0;" : "+l"(d) : "l"(a), "l"(b));
}
__device__ __forceinline__ ull addp2(ull a, ull b) {
    ull r; asm("add.rn.f32x2 %0, %1, %2;" : "=l"(r) : "l"(a), "l"(b)); return r;
}
__device__ __forceinline__ ull pack2(float x, float y) {
    ull r; asm("mov.b64 %0, {%1, %2};" : "=l"(r) : "f"(x), "f"(y)); return r;
}
__device__ __forceinline__ float2 unpack2(ull v) {
    float2 r; asm("mov.b64 {%0, %1}, %2;" : "=f"(r.x), "=f"(r.y) : "l"(v)); return r;
}

// Fast-but-accurate tanh: 1 - 2/(exp(2x)+1). abs err ~1e-6.
__device__ __forceinline__ float fast_tanh(float x) {
    float e = __expf(x * 2.0f);
    return 1.0f - __fdividef(2.0f, e + 1.0f);
}

// =====================================================================
// Kernel 1: fused encoder+decoder scan with cross-group pipelining.
// 128 CTAs x 256 threads; grp = tid>>7 = row, j = tid&127 = unit.
// Intra-group step sync: named barriers 1 (grp0) / 2 (grp1).
// Cross-group anti-phase handshake: grp0 arrives on barrier 3 right
// after its dot issues; grp1 waits on 3 before its dot; grp1 arrives
// on 4 after its dot; grp0 waits on 4 (primed once before the loop).
// => the two groups' FFMA2-issue phases and tails interleave:
//    T = max(384, 192 + tail) instead of 384 + tail.
// =====================================================================
__global__ void __launch_bounds__(256, 1) scan_kernel(
    const int*   __restrict__ enc_ids, const int* __restrict__ dec_ids,
    const float* __restrict__ embed,
    const float* __restrict__ enc_Wx, const float* __restrict__ enc_Wh,
    const float* __restrict__ enc_b,
    const float* __restrict__ dec_Wx, const float* __restrict__ dec_Wh,
    const float* __restrict__ dec_b)
{
    __shared__ float tabE[VV][HH];
    __shared__ float tabD[VV][HH];
    __shared__ float emb_s[VV * EE];
    __shared__ __align__(16) float hbuf[2][2][HH];
    __shared__ int   idsE[2][SE];
    __shared__ int   idsD[2][SD];

    const int tid  = threadIdx.x;
    const int grp  = tid >> 7;
    const int j    = tid & (HH - 1);
    const int row0 = blockIdx.x * 2;
    const int row  = row0 + grp;

    for (int i = tid; i < VV * EE; i += 256) emb_s[i] = embed[i];
    for (int i = tid; i < SE; i += 256) {
        idsE[0][i] = enc_ids[(size_t)row0 * SE + i];
        idsE[1][i] = enc_ids[(size_t)(row0 + 1) * SE + i];
    }
    for (int i = tid; i < SD; i += 256) {
        idsD[0][i] = dec_ids[(size_t)row0 * SD + i];
        idsD[1][i] = dec_ids[(size_t)(row0 + 1) * SD + i];
    }
    __syncthreads();

    for (int idx = tid; idx < VV * HH; idx += 256) {
        const int v = idx / HH;
        const int h = idx - v * HH;
        float sE = enc_b[h];
        float sD = dec_b[h];
        #pragma unroll 8
        for (int e = 0; e < EE; e++) {
            const float em = emb_s[v * EE + e];
            sE = fmaf(em, enc_Wx[e * HH + h], sE);
            sD = fmaf(em, dec_Wx[e * HH + h], sD);
        }
        tabE[v][h] = sE;
        tabD[v][h] = sD;
    }

    if (grp == 0) { hbuf[0][0][j] = 0.0f; hbuf[0][1][j] = 0.0f; }
    __syncthreads();

    ull w2[HH / 2];
    #pragma unroll
    for (int k = 0; k < HH / 2; k++)
        w2[k] = pack2(enc_Wh[(2 * k) * HH + j], enc_Wh[(2 * k + 1) * HH + j]);

    // prime the ring: grp1 deposits one token on barrier 4 so grp0's
    // first wait passes. Counts per phase: 128 arrives + 128 syncs = 256.
    if (grp == 1)
        asm volatile("bar.arrive 4, 256;" ::: "memory");

    // ---- encoder phase ----
    int cur = 0;
    float tb = tabE[idsE[grp][0]][j];
    for (int t = 0; t < SE; t++) {
        // cross-group gate: start my dot only when the other group's
        // dot has finished issuing (its token is up).
        if (grp == 0) asm volatile("bar.sync 4, 256;" ::: "memory");
        else          asm volatile("bar.sync 3, 256;" ::: "memory");

        const ulonglong2* hq = (const ulonglong2*)hbuf[cur][grp];
        ull a0 = pack2(tb, 0.0f), a1 = 0, a2 = 0, a3 = 0;
        #pragma unroll
        for (int q = 0; q < HH / 4; q += 2) {
            ulonglong2 h0 = hq[q];
            ulonglong2 h1 = hq[q + 1];
            ffma2(a0, h0.x, w2[2 * q + 0]);
            ffma2(a1, h0.y, w2[2 * q + 1]);
            ffma2(a2, h1.x, w2[2 * q + 2]);
            ffma2(a3, h1.y, w2[2 * q + 3]);
        }
        float2 s = unpack2(addp2(addp2(a0, a2), addp2(a1, a3)));
        const float pre = s.x + s.y;
        // token up: my issue phase is done (pre depends on every FFMA2)
        if (grp == 0) asm volatile("bar.arrive 3, 256;" :: "f"(pre));
        else          asm volatile("bar.arrive 4, 256;" :: "f"(pre));

        const int tn = (t + 1 < SE) ? t + 1 : t;
        const float nb = tabE[idsE[grp][tn]][j];
        const float hn = fast_tanh(pre);
        hbuf[cur ^ 1][grp][j] = hn;
        asm volatile("bar.sync %0, 128;" :: "r"(grp + 1) : "memory");
        cur ^= 1;
        tb = nb;
    }

    // ---- decoder phase ----
    #pragma unroll
    for (int k = 0; k < HH / 2; k++)
        w2[k] = pack2(dec_Wh[(2 * k) * HH + j], dec_Wh[(2 * k + 1) * HH + j]);

    __half* outrow = g_dec_h + (size_t)row * SD * HH;
    tb = tabD[idsD[grp][0]][j];
    for (int t = 0; t < SD; t++) {
        if (grp == 0) asm volatile("bar.sync 4, 256;" ::: "memory");
        else          asm volatile("bar.sync 3, 256;" ::: "memory");

        const ulonglong2* hq = (const ulonglong2*)hbuf[cur][grp];
        ull a0 = pack2(tb, 0.0f), a1 = 0, a2 = 0, a3 = 0;
        #pragma unroll
        for (int q = 0; q < HH / 4; q += 2) {
            ulonglong2 h0 = hq[q];
            ulonglong2 h1 = hq[q + 1];
            ffma2(a0, h0.x, w2[2 * q + 0]);
            ffma2(a1, h0.y, w2[2 * q + 1]);
            ffma2(a2, h1.x, w2[2 * q + 2]);
            ffma2(a3, h1.y, w2[2 * q + 3]);
        }
        float2 s = unpack2(addp2(addp2(a0, a2), addp2(a1, a3)));
        const float pre = s.x + s.y;
        if (grp == 0) asm volatile("bar.arrive 3, 256;" :: "f"(pre));
        else          asm volatile("bar.arrive 4, 256;" :: "f"(pre));

        const int tn = (t + 1 < SD) ? t + 1 : t;
        const float nb = tabD[idsD[grp][tn]][j];
        const float hn = fast_tanh(pre);
        hbuf[cur ^ 1][grp][j] = hn;
        asm volatile("bar.sync %0, 128;" :: "r"(grp + 1) : "memory");
        outrow[t * HH + j] = __float2half_rn(hn);   // off-chain store
        cur ^= 1;
        tb = nb;
    }
}

// =====================================================================
// Kernel 2: logits via tensor cores, 64-token tiles (2048 CTAs x 128
// threads = 4 warps, warp w owns rows 16w..16w+15). h fp16 staged in
// padded smem; W^T fp16 in smem; fp32 MMA accumulate. Epilogue stages
// the 64x27 logit tile in smem, then writes it as 432 coalesced
// float4 (tile is contiguous in out).
// =====================================================================
__global__ void __launch_bounds__(128) logits_kernel(
    const float* __restrict__ dense_W, const float* __restrict__ dense_b,
    float* __restrict__ out)
{
    __shared__ __align__(16) __half hs[64 * 136];    // 17 KB h tile
    __shared__ __align__(16) __half w_s[32 * 136];   // 8.5 KB W^T
    __shared__ __align__(16) float  Ls[64 * VV];     // 6.9 KB logit tile
    __shared__ float bias_s[32];

    const int tid  = threadIdx.x;
    const int lane = tid & 31;
    const int wid  = tid >> 5;            // 0..3
    const size_t tok0 = (size_t)blockIdx.x * 64;

    // stage h tile: 1024 uint4 (16 per token row), 8 per thread
    const uint4* src = (const uint4*)(g_dec_h + tok0 * HH);
    #pragma unroll
    for (int i = 0; i < 8; i++) {
        const int idx = tid + 128 * i;
        const int row = idx >> 4, part = idx & 15;
        *(uint4*)&hs[row * 136 + part * 8] = src[idx];
    }

    // stage W^T fp16: w_s[v][k] = W[k][v]; pad v>=27 with 0
    for (int idx = tid; idx < 32 * 128; idx += 128) {
        const int v = idx & 31, k = idx >> 5;
        const float val = (v < VV) ? dense_W[k * VV + v] : 0.0f;
        w_s[v * 136 + k] = __float2half_rn(val);
    }
    if (tid < 32) bias_s[tid] = (tid < VV) ? dense_b[tid] : 0.0f;
    __syncthreads();

    const int gi = lane >> 2;      // groupID
    const int ci = lane & 3;       // thread-in-group
    const int m0 = wid * 16;

    float c[4][4] = {};
    #pragma unroll
    for (int ks = 0; ks < 8; ks++) {
        const int k = ks * 16 + ci * 2;
        const u32 a0 = *(const u32*)&hs[(m0 + gi)     * 136 + k];
        const u32 a1 = *(const u32*)&hs[(m0 + gi + 8) * 136 + k];
        const u32 a2 = *(const u32*)&hs[(m0 + gi)     * 136 + k + 8];
        const u32 a3 = *(const u32*)&hs[(m0 + gi + 8) * 136 + k + 8];
        #pragma unroll
        for (int nt = 0; nt < 4; nt++) {
            const int cc = nt * 8 + gi;
            const u32 b0 = *(const u32*)&w_s[cc * 136 + k];
            const u32 b1 = *(const u32*)&w_s[cc * 136 + k + 8];
            asm volatile(
                "mma.sync.aligned.m16n8k16.row.col.f32.f16.f16.f32 "
                "{%0,%1,%2,%3}, {%4,%5,%6,%7}, {%8,%9}, {%0,%1,%2,%3};"
                : "+f"(c[nt][0]), "+f"(c[nt][1]), "+f"(c[nt][2]), "+f"(c[nt][3])
                : "r"(a0), "r"(a1), "r"(a2), "r"(a3), "r"(b0), "r"(b1));
        }
    }

    // epilogue: fragments -> smem logit tile (with bias)
    #pragma unroll
    for (int nt = 0; nt < 4; nt++) {
        const int col = nt * 8 + ci * 2;
        const int r0 = m0 + gi;
        if (col < VV) {
            Ls[r0 * VV + col]       = c[nt][0] + bias_s[col];
            Ls[(r0 + 8) * VV + col] = c[nt][2] + bias_s[col];
        }
        if (col + 1 < VV) {
            Ls[r0 * VV + col + 1]       = c[nt][1] + bias_s[col + 1];
            Ls[(r0 + 8) * VV + col + 1] = c[nt][3] + bias_s[col + 1];
        }
    }
    __syncthreads();

    // tile is contiguous in out: 64*27 floats = 432 float4, coalesced
    float4* dst = (float4*)(out + tok0 * VV);
    const float4* srcL = (const float4*)Ls;
    #pragma unroll
    for (int i = 0; i < 4; i++) {
        const int idx = tid + 128 * i;
        if (idx < (64 * VV) / 4) dst[idx] = srcL[idx];
    }
}

// =====================================================================
extern "C" void kernel_launch(void* const* d_in, const int* in_sizes, int n_in,
                              void* d_out, int out_size) {
    const int*   enc_ids = (const int*)  d_in[0];
    const int*   dec_ids = (const int*)  d_in[1];
    const float* embed   = (const float*)d_in[2];
    const float* enc_Wx  = (const float*)d_in[3];
    const float* enc_Wh  = (const float*)d_in[4];
    const float* enc_b   = (const float*)d_in[5];
    const float* dec_Wx  = (const float*)d_in[6];
    const float* dec_Wh  = (const float*)d_in[7];
    const float* dec_b   = (const float*)d_in[8];
    const float* dense_W = (const float*)d_in[9];
    const float* dense_b = (const float*)d_in[10];
    float* out = (float*)d_out;

    scan_kernel<<<BB / 2, 256>>>(enc_ids, dec_ids, embed,
                                 enc_Wx, enc_Wh, enc_b,
                                 dec_Wx, dec_Wh, dec_b);
    logits_kernel<<<(BB * SD) / 64, 128>>>(dense_W, dense_b, out);
}

// round 10
// speedup vs baseline: 1.9782x; 1.0865x over previous
#include <cuda_runtime.h>
#include <cuda_fp16.h>
#include <cstdint>
#include <math.h>

// Problem constants
#define VV 27
#define EE 64
#define HH 128
#define BB 256
#define SE 512
#define SD 512

typedef unsigned long long ull;
typedef unsigned int u32;

// Scratch for decoder hidden states, fp16: [B, S_DEC, H] = 32 MB.
__device__ __half g_dec_h[(size_t)BB * SD * HH];

// ---- packed fp32x2 helpers (sm_103a FFMA2 / FADD2) ----
__device__ __forceinline__ void ffma2(ull& d, ull a, ull b) {
    asm("fma.rn.f32x2 %0, %1, %2, %0;" : "+l"(d) : "l"(a), "l"(b));
}
__device__ __forceinline__ ull addp2(ull a, ull b) {
    ull r; asm("add.rn.f32x2 %0, %1, %2;" : "=l"(r) : "l"(a), "l"(b)); return r;
}
__device__ __forceinline__ ull pack2(float x, float y) {
    ull r; asm("mov.b64 %0, {%1, %2};" : "=l"(r) : "f"(x), "f"(y)); return r;
}
__device__ __forceinline__ float2 unpack2(ull v) {
    float2 r; asm("mov.b64 {%0, %1}, %2;" : "=f"(r.x), "=f"(r.y) : "l"(v)); return r;
}

// Fast-but-accurate tanh: 1 - 2/(exp(2x)+1). abs err ~1e-6.
__device__ __forceinline__ float fast_tanh(float x) {
    float e = __expf(x * 2.0f);
    return 1.0f - __fdividef(2.0f, e + 1.0f);
}

// =====================================================================
// Kernel 1: fused encoder+decoder scan, minimal-barrier pipeline.
// 128 CTAs x 256 threads; grp = tid>>7 = row, j = tid&127 = unit.
// ONE blocking barrier per group per step:
//   grp0:  bar.sync 4 -> dot -> bar.arrive 3 -> tanh/STS
//   grp1:  bar.sync 3 -> dot -> bar.arrive 4 -> tanh/STS
// bar.sync N,256 (128 syncers + 128 arrivers) both gates on the other
// group's dot AND mutually synchronizes the syncing group's threads,
// so it carries the STS->LDS ordering: the old intra-group bar.sync
// 1/2 was redundant and is removed.
// =====================================================================
__global__ void __launch_bounds__(256, 1) scan_kernel(
    const int*   __restrict__ enc_ids, const int* __restrict__ dec_ids,
    const float* __restrict__ embed,
    const float* __restrict__ enc_Wx, const float* __restrict__ enc_Wh,
    const float* __restrict__ enc_b,
    const float* __restrict__ dec_Wx, const float* __restrict__ dec_Wh,
    const float* __restrict__ dec_b)
{
    __shared__ float tabE[VV][HH];
    __shared__ float tabD[VV][HH];
    __shared__ float emb_s[VV * EE];
    __shared__ __align__(16) float hbuf[2][2][HH];
    __shared__ int   idsE[2][SE];
    __shared__ int   idsD[2][SD];

    const int tid  = threadIdx.x;
    const int grp  = tid >> 7;
    const int j    = tid & (HH - 1);
    const int row0 = blockIdx.x * 2;
    const int row  = row0 + grp;

    for (int i = tid; i < VV * EE; i += 256) emb_s[i] = embed[i];
    for (int i = tid; i < SE; i += 256) {
        idsE[0][i] = enc_ids[(size_t)row0 * SE + i];
        idsE[1][i] = enc_ids[(size_t)(row0 + 1) * SE + i];
    }
    for (int i = tid; i < SD; i += 256) {
        idsD[0][i] = dec_ids[(size_t)row0 * SD + i];
        idsD[1][i] = dec_ids[(size_t)(row0 + 1) * SD + i];
    }
    __syncthreads();

    for (int idx = tid; idx < VV * HH; idx += 256) {
        const int v = idx / HH;
        const int h = idx - v * HH;
        float sE = enc_b[h];
        float sD = dec_b[h];
        #pragma unroll 8
        for (int e = 0; e < EE; e++) {
            const float em = emb_s[v * EE + e];
            sE = fmaf(em, enc_Wx[e * HH + h], sE);
            sD = fmaf(em, dec_Wx[e * HH + h], sD);
        }
        tabE[v][h] = sE;
        tabD[v][h] = sD;
    }

    if (grp == 0) { hbuf[0][0][j] = 0.0f; hbuf[0][1][j] = 0.0f; }
    __syncthreads();

    ull w2[HH / 2];
    #pragma unroll
    for (int k = 0; k < HH / 2; k++)
        w2[k] = pack2(enc_Wh[(2 * k) * HH + j], enc_Wh[(2 * k + 1) * HH + j]);

    // prime the ring: grp1 deposits one token on barrier 4 so grp0's
    // first wait passes.
    if (grp == 1)
        asm volatile("bar.arrive 4, 256;" ::: "memory");

    // ---- encoder phase ----
    int cur = 0;
    float tb = tabE[idsE[grp][0]][j];
    for (int t = 0; t < SE; t++) {
        // single blocking barrier: cross-group gate + intra-group sync
        if (grp == 0) asm volatile("bar.sync 4, 256;" ::: "memory");
        else          asm volatile("bar.sync 3, 256;" ::: "memory");

        const ulonglong2* hq = (const ulonglong2*)hbuf[cur][grp];
        ull a0 = pack2(tb, 0.0f), a1 = 0, a2 = 0, a3 = 0;
        #pragma unroll
        for (int q = 0; q < HH / 4; q += 2) {
            ulonglong2 h0 = hq[q];
            ulonglong2 h1 = hq[q + 1];
            ffma2(a0, h0.x, w2[2 * q + 0]);
            ffma2(a1, h0.y, w2[2 * q + 1]);
            ffma2(a2, h1.x, w2[2 * q + 2]);
            ffma2(a3, h1.y, w2[2 * q + 3]);
        }
        float2 s = unpack2(addp2(addp2(a0, a2), addp2(a1, a3)));
        const float pre = s.x + s.y;
        // token up: my issue phase done (pre depends on every FFMA2)
        if (grp == 0) asm volatile("bar.arrive 3, 256;" :: "f"(pre));
        else          asm volatile("bar.arrive 4, 256;" :: "f"(pre));

        const int tn = (t + 1 < SE) ? t + 1 : t;
        const float nb = tabE[idsE[grp][tn]][j];
        const float hn = fast_tanh(pre);
        hbuf[cur ^ 1][grp][j] = hn;
        cur ^= 1;
        tb = nb;
    }

    // ---- decoder phase ----
    #pragma unroll
    for (int k = 0; k < HH / 2; k++)
        w2[k] = pack2(dec_Wh[(2 * k) * HH + j], dec_Wh[(2 * k + 1) * HH + j]);

    __half* outrow = g_dec_h + (size_t)row * SD * HH;
    tb = tabD[idsD[grp][0]][j];
    for (int t = 0; t < SD; t++) {
        if (grp == 0) asm volatile("bar.sync 4, 256;" ::: "memory");
        else          asm volatile("bar.sync 3, 256;" ::: "memory");

        const ulonglong2* hq = (const ulonglong2*)hbuf[cur][grp];
        ull a0 = pack2(tb, 0.0f), a1 = 0, a2 = 0, a3 = 0;
        #pragma unroll
        for (int q = 0; q < HH / 4; q += 2) {
            ulonglong2 h0 = hq[q];
            ulonglong2 h1 = hq[q + 1];
            ffma2(a0, h0.x, w2[2 * q + 0]);
            ffma2(a1, h0.y, w2[2 * q + 1]);
            ffma2(a2, h1.x, w2[2 * q + 2]);
            ffma2(a3, h1.y, w2[2 * q + 3]);
        }
        float2 s = unpack2(addp2(addp2(a0, a2), addp2(a1, a3)));
        const float pre = s.x + s.y;
        if (grp == 0) asm volatile("bar.arrive 3, 256;" :: "f"(pre));
        else          asm volatile("bar.arrive 4, 256;" :: "f"(pre));

        const int tn = (t + 1 < SD) ? t + 1 : t;
        const float nb = tabD[idsD[grp][tn]][j];
        const float hn = fast_tanh(pre);
        hbuf[cur ^ 1][grp][j] = hn;
        outrow[t * HH + j] = __float2half_rn(hn);   // off-chain store
        cur ^= 1;
        tb = nb;
    }
}

// =====================================================================
// Kernel 2: logits via tensor cores, 128-token tiles, 1024 CTAs x 256
// threads (8 warps, warp w owns rows 16w..16w+15). Logit tile Ls
// ALIASES the h tile (hs is dead after the MMA fragment loads; a
// __syncthreads separates the lifetimes) to stay under the 48KB
// static-smem cap. Coalesced float4 epilogue.
// =====================================================================
__global__ void __launch_bounds__(256) logits_kernel(
    const float* __restrict__ dense_W, const float* __restrict__ dense_b,
    float* __restrict__ out)
{
    __shared__ __align__(16) __half hs[128 * 136];   // 34 KB h tile
    __shared__ __align__(16) __half w_s[32 * 136];   // 8.5 KB W^T
    __shared__ float bias_s[32];
    float* Ls = (float*)hs;   // 128*27*4 = 13.8 KB, aliases dead hs

    const int tid  = threadIdx.x;
    const int lane = tid & 31;
    const int wid  = tid >> 5;            // 0..7
    const size_t tok0 = (size_t)blockIdx.x * 128;

    // stage h tile: 2048 uint4 (16 per token row), 8 per thread
    const uint4* src = (const uint4*)(g_dec_h + tok0 * HH);
    #pragma unroll
    for (int i = 0; i < 8; i++) {
        const int idx = tid + 256 * i;
        const int row = idx >> 4, part = idx & 15;
        *(uint4*)&hs[row * 136 + part * 8] = src[idx];
    }

    // stage W^T fp16: w_s[v][k] = W[k][v]; pad v>=27 with 0
    for (int idx = tid; idx < 32 * 128; idx += 256) {
        const int v = idx & 31, k = idx >> 5;
        const float val = (v < VV) ? dense_W[k * VV + v] : 0.0f;
        w_s[v * 136 + k] = __float2half_rn(val);
    }
    if (tid < 32) bias_s[tid] = (tid < VV) ? dense_b[tid] : 0.0f;
    __syncthreads();

    const int gi = lane >> 2;      // groupID
    const int ci = lane & 3;       // thread-in-group
    const int m0 = wid * 16;

    float c[4][4] = {};
    #pragma unroll
    for (int ks = 0; ks < 8; ks++) {
        const int k = ks * 16 + ci * 2;
        const u32 a0 = *(const u32*)&hs[(m0 + gi)     * 136 + k];
        const u32 a1 = *(const u32*)&hs[(m0 + gi + 8) * 136 + k];
        const u32 a2 = *(const u32*)&hs[(m0 + gi)     * 136 + k + 8];
        const u32 a3 = *(const u32*)&hs[(m0 + gi + 8) * 136 + k + 8];
        #pragma unroll
        for (int nt = 0; nt < 4; nt++) {
            const int cc = nt * 8 + gi;
            const u32 b0 = *(const u32*)&w_s[cc * 136 + k];
            const u32 b1 = *(const u32*)&w_s[cc * 136 + k + 8];
            asm volatile(
                "mma.sync.aligned.m16n8k16.row.col.f32.f16.f16.f32 "
                "{%0,%1,%2,%3}, {%4,%5,%6,%7}, {%8,%9}, {%0,%1,%2,%3};"
                : "+f"(c[nt][0]), "+f"(c[nt][1]), "+f"(c[nt][2]), "+f"(c[nt][3])
                : "r"(a0), "r"(a1), "r"(a2), "r"(a3), "r"(b0), "r"(b1));
        }
    }

    // hs is dead from here; Ls takes over the storage
    __syncthreads();

    #pragma unroll
    for (int nt = 0; nt < 4; nt++) {
        const int col = nt * 8 + ci * 2;
        const int r0 = m0 + gi;
        if (col < VV) {
            Ls[r0 * VV + col]       = c[nt][0] + bias_s[col];
            Ls[(r0 + 8) * VV + col] = c[nt][2] + bias_s[col];
        }
        if (col + 1 < VV) {
            Ls[r0 * VV + col + 1]       = c[nt][1] + bias_s[col + 1];
            Ls[(r0 + 8) * VV + col + 1] = c[nt][3] + bias_s[col + 1];
        }
    }
    __syncthreads();

    // tile contiguous in out: 128*27 floats = 864 float4, coalesced
    float4* dst = (float4*)(out + tok0 * VV);
    const float4* srcL = (const float4*)Ls;
    #pragma unroll
    for (int i = 0; i < 4; i++) {
        const int idx = tid + 256 * i;
        if (idx < (128 * VV) / 4) dst[idx] = srcL[idx];
    }
}

// =====================================================================
extern "C" void kernel_launch(void* const* d_in, const int* in_sizes, int n_in,
                              void* d_out, int out_size) {
    const int*   enc_ids = (const int*)  d_in[0];
    const int*   dec_ids = (const int*)  d_in[1];
    const float* embed   = (const float*)d_in[2];
    const float* enc_Wx  = (const float*)d_in[3];
    const float* enc_Wh  = (const float*)d_in[4];
    const float* enc_b   = (const float*)d_in[5];
    const float* dec_Wx  = (const float*)d_in[6];
    const float* dec_Wh  = (const float*)d_in[7];
    const float* dec_b   = (const float*)d_in[8];
    const float* dense_W = (const float*)d_in[9];
    const float* dense_b = (const float*)d_in[10];
    float* out = (float*)d_out;

    scan_kernel<<<BB / 2, 256>>>(enc_ids, dec_ids, embed,
                                 enc_Wx, enc_Wh, enc_b,
                                 dec_Wx, dec_Wh, dec_b);
    logits_kernel<<<(BB * SD) / 128, 256>>>(dense_W, dense_b, out);
}